// round 7
// baseline (speedup 1.0000x reference)
#include <cuda_runtime.h>
#include <cuda_bf16.h>
#include <stdint.h>

// ---------------- problem constants ----------------
#define B_TOT   4096
#define F0N     39
#define DN      16
#define NT      256

#define K0TOT   1521      // 39*39
#define K0PAD   1536      // 24 chunks of 64
#define K1TOT   2496      // 39*64
#define K1PAD   2496      // 39 chunks of 64

#define BK      64        // K per chunk (bf16 elems)
#define BKP     72        // padded row length (bf16) for A/B tiles -> 144B stride
#define IPAD    41        // xs_T row stride (floats)
#define JPAD    65        // hs_T row stride (floats)

// ---------------- global scratch ----------------
__device__ float         g_h[B_TOT * 64 * DN];
__device__ __nv_bfloat16 g_w0hi[128 * K0PAD];
__device__ __nv_bfloat16 g_w0lo[128 * K0PAD];
__device__ __nv_bfloat16 g_w1hi[128 * K1PAD];
__device__ __nv_bfloat16 g_w1lo[128 * K1PAD];

// ---------------- PTX helpers ----------------
__device__ __forceinline__ uint32_t smem_to_u32(const void* p) {
    uint32_t a;
    asm("{ .reg .u64 t; cvta.to.shared.u64 t, %1; cvt.u32.u64 %0, t; }" : "=r"(a) : "l"(p));
    return a;
}

__device__ __forceinline__ void ldsm4(uint32_t* r, uint32_t addr) {
    asm volatile("ldmatrix.sync.aligned.m8n8.x4.shared.b16 {%0,%1,%2,%3}, [%4];"
        : "=r"(r[0]), "=r"(r[1]), "=r"(r[2]), "=r"(r[3]) : "r"(addr));
}

__device__ __forceinline__ void mma_bf16(float* c, const uint32_t* a, uint32_t b0, uint32_t b1) {
    asm volatile(
        "mma.sync.aligned.m16n8k16.row.col.f32.bf16.bf16.f32 "
        "{%0,%1,%2,%3}, {%4,%5,%6,%7}, {%8,%9}, {%0,%1,%2,%3};"
        : "+f"(c[0]), "+f"(c[1]), "+f"(c[2]), "+f"(c[3])
        : "r"(a[0]), "r"(a[1]), "r"(a[2]), "r"(a[3]), "r"(b0), "r"(b1));
}

#define CP_ASYNC16(saddr, gptr) \
    asm volatile("cp.async.cg.shared.global [%0], [%1], 16;" \
        :: "r"((uint32_t)(saddr)), "l"(gptr))
#define CP_COMMIT()  asm volatile("cp.async.commit_group;" ::: "memory")
#define CP_WAIT0()   asm volatile("cp.async.wait_group 0;"  ::: "memory")

// ---------------- W pre-split: f[k][128] -> g_w{hi,lo} [n=128][KPAD], zero-padded ----------------
template<int LAYER>
__global__ void __launch_bounds__(256)
convert_w_kernel(const float* __restrict__ f)
{
    constexpr int KTOT = (LAYER == 0) ? K0TOT : K1TOT;
    constexpr int KPAD = (LAYER == 0) ? K0PAD : K1PAD;
    __nv_bfloat16* whi = (LAYER == 0) ? g_w0hi : g_w1hi;
    __nv_bfloat16* wlo = (LAYER == 0) ? g_w0lo : g_w1lo;

    int idx = blockIdx.x * blockDim.x + threadIdx.x;
    if (idx >= 128 * KPAD) return;
    int n = idx / KPAD;
    int k = idx - n * KPAD;
    float v = (k < KTOT) ? f[k * 128 + n] : 0.0f;
    __nv_bfloat16 h = __float2bfloat16_rn(v);
    float r = v - __bfloat162float(h);
    whi[idx] = h;
    wlo[idx] = __float2bfloat16_rn(r);
}

// ---------------- main fused layer kernel (HMMA, software-pipelined) ----------------
template<int FK, int KTOT, int KPAD, int LAYER>
__global__ void __launch_bounds__(NT)
cin_mma_kernel(const float* __restrict__ x,
               const float* __restrict__ dw,
               const float* __restrict__ db,
               float* __restrict__ out)
{
    extern __shared__ char smem[];

    constexpr int OFF_DW   = 0;                    // 192 floats
    constexpr int OFF_SOUT = 768;                  // 8 floats
    constexpr int OFF_XT   = 1024;                 // [128][IPAD] floats
    constexpr int XT_BYTES = 128 * IPAD * 4;       // 20992
    constexpr int OFF_HT   = OFF_XT + XT_BYTES;
    constexpr int HT_BYTES = (LAYER == 1) ? 128 * JPAD * 4 : 0;
    constexpr int OFF_T    = ((OFF_HT + HT_BYTES + 1023) / 1024) * 1024;
    constexpr int TILE_B   = 128 * BKP * 2;        // 18432
    constexpr int BUF_STRIDE = 4 * TILE_B;         // Ahi Alo Bhi Blo per buffer
    constexpr int NCHUNKS  = KPAD / BK;

    const __nv_bfloat16* __restrict__ whi = (LAYER == 0) ? g_w0hi : g_w1hi;
    const __nv_bfloat16* __restrict__ wlo = (LAYER == 0) ? g_w0lo : g_w1lo;

    const uint32_t smem_u = smem_to_u32(smem);
    float* s_dw  = (float*)(smem + OFF_DW);
    float* s_out = (float*)(smem + OFF_SOUT);
    float* xt    = (float*)(smem + OFF_XT);
    float* ht    = (LAYER == 0) ? xt : (float*)(smem + OFF_HT);
    constexpr int HSTR = (LAYER == 0) ? IPAD : JPAD;

    const int tid  = threadIdx.x;
    const int wid  = tid >> 5;
    const int lane = tid & 31;
    const int b0   = blockIdx.x * 8;

    // ---- stage x transposed: xt[row][i], row = bl*16 + d ----
    for (int e = tid; e < 8 * F0N * DN; e += NT) {
        int bl = e / (F0N * DN);
        int rem = e - bl * (F0N * DN);
        int i = rem >> 4, d = rem & 15;
        xt[(bl * 16 + d) * IPAD + i] = x[(size_t)(b0) * (F0N * DN) + e];
    }
    if (LAYER == 1) {
        for (int e = tid; e < 8 * 64 * 16; e += NT) {
            int bl = e >> 10;
            int j  = (e >> 4) & 63;
            int d  = e & 15;
            ht[(bl * 16 + d) * JPAD + j] = g_h[(size_t)b0 * 1024 + e];
        }
    }
    if (tid < 192) s_dw[tid] = dw[tid];
    if (tid < 8)   s_out[tid] = 0.0f;
    __syncthreads();

    // warp tiling: 4 (M) x 2 (N); warp tile 32 x 64
    const int wm = wid >> 1;
    const int wn = wid & 1;
    const int m0 = wm * 32;
    const int n0 = wn * 64;

    float acc[2][8][4];
#pragma unroll
    for (int mt = 0; mt < 2; mt++)
#pragma unroll
        for (int nt = 0; nt < 8; nt++)
#pragma unroll
            for (int r = 0; r < 4; r++) acc[mt][nt][r] = 0.0f;

    const int srow = tid >> 3;     // 0..31 (+part*32)
    const int skt  = tid & 7;      // 0..7 (8 bf16 each)
    const float* xr_base = xt;
    const float* hr_base = ht;

    // build one part (32 rows) of the A chunk for k-base k0n into buffer at Abase
    auto build_part = [&](int k0n, int part, char* AhiB, char* AloB) {
        int row = srow + part * 32;
        int kb  = k0n + skt * 8;
        const float* xr = xr_base + row * IPAD;
        const float* hr = hr_base + row * HSTR;
        uint32_t hp[4], lp[4];
#pragma unroll
        for (int v = 0; v < 4; v++) {
            float p0 = 0.0f, p1 = 0.0f;
            int ka = kb + 2 * v;
            if (KPAD == KTOT || ka < KTOT) {
                int i = ka / FK, j = ka - i * FK;
                p0 = xr[i] * hr[j];
            }
            if (KPAD == KTOT || (ka + 1) < KTOT) {
                int i = (ka + 1) / FK, j = (ka + 1) - i * FK;
                p1 = xr[i] * hr[j];
            }
            __nv_bfloat16 h0 = __float2bfloat16_rn(p0);
            __nv_bfloat16 h1 = __float2bfloat16_rn(p1);
            __nv_bfloat16 e0 = __float2bfloat16_rn(p0 - __bfloat162float(h0));
            __nv_bfloat16 e1 = __float2bfloat16_rn(p1 - __bfloat162float(h1));
            hp[v] = (uint32_t)__bfloat16_as_ushort(h0) | ((uint32_t)__bfloat16_as_ushort(h1) << 16);
            lp[v] = (uint32_t)__bfloat16_as_ushort(e0) | ((uint32_t)__bfloat16_as_ushort(e1) << 16);
        }
        uint32_t so = (uint32_t)(row * (BKP * 2) + skt * 16);
        *(uint4*)(AhiB + so) = make_uint4(hp[0], hp[1], hp[2], hp[3]);
        *(uint4*)(AloB + so) = make_uint4(lp[0], lp[1], lp[2], lp[3]);
    };

    auto issue_b = [&](int k0n, int pbuf) {
        char* Bhi = smem + OFF_T + pbuf * BUF_STRIDE + 2 * TILE_B;
        char* Blo = Bhi + TILE_B;
        uint32_t bhi_u = smem_u + (uint32_t)(Bhi - smem);
        uint32_t blo_u = smem_u + (uint32_t)(Blo - smem);
#pragma unroll
        for (int p = 0; p < 4; p++) {
            int n = srow + p * 32;
            uint32_t so = (uint32_t)(n * (BKP * 2) + skt * 16);
            CP_ASYNC16(bhi_u + so, whi + (size_t)n * KPAD + k0n + skt * 8);
            CP_ASYNC16(blo_u + so, wlo + (size_t)n * KPAD + k0n + skt * 8);
        }
    };

    // ---- prologue: chunk 0 into buffer 0 ----
    issue_b(0, 0);
    CP_COMMIT();
#pragma unroll
    for (int part = 0; part < 4; part++)
        build_part(0, part, smem + OFF_T, smem + OFF_T + TILE_B);
    CP_WAIT0();
    __syncthreads();

    const int lrow = (lane & 7) + ((lane >> 3) & 1) * 8;
    const int lkb  = (lane >> 4) * 16;

    for (int ch = 0; ch < NCHUNKS; ch++) {
        const int p = ch & 1;
        const bool have_next = (ch + 1 < NCHUNKS);
        const int k0n = (ch + 1) * BK;
        char* cur  = smem + OFF_T + p * BUF_STRIDE;
        char* nxt  = smem + OFF_T + (p ^ 1) * BUF_STRIDE;
        const uint32_t cur_u = smem_u + (uint32_t)(OFF_T + p * BUF_STRIDE);

        if (have_next) { issue_b(k0n, p ^ 1); CP_COMMIT(); }

        // ---- 4 k16-steps of MMA on buffer p, interleaved with building A(ch+1) ----
#pragma unroll
        for (int ks = 0; ks < 4; ks++) {
            if (have_next)
                build_part(k0n, ks, nxt, nxt + TILE_B);

            const uint32_t kcb = (uint32_t)(ks * 32 + lkb);
            uint32_t ah[2][4], al[2][4];
#pragma unroll
            for (int mt = 0; mt < 2; mt++) {
                uint32_t ra = (uint32_t)((m0 + mt * 16 + lrow) * (BKP * 2)) + kcb;
                ldsm4(ah[mt], cur_u + ra);                       // Ahi
                ldsm4(al[mt], cur_u + TILE_B + ra);              // Alo
            }
#pragma unroll
            for (int nt2 = 0; nt2 < 4; nt2++) {
                uint32_t rb = (uint32_t)((n0 + nt2 * 16 + lrow) * (BKP * 2)) + kcb;
                uint32_t bh[4], blr[4];
                ldsm4(bh,  cur_u + 2 * TILE_B + rb);             // Bhi
                ldsm4(blr, cur_u + 3 * TILE_B + rb);             // Blo
#pragma unroll
                for (int mt = 0; mt < 2; mt++) {
#pragma unroll
                    for (int sub = 0; sub < 2; sub++) {
                        float* c = acc[mt][nt2 * 2 + sub];
                        mma_bf16(c, ah[mt], bh[sub],  bh[sub + 2]);   // hi*hi
                        mma_bf16(c, ah[mt], blr[sub], blr[sub + 2]);  // hi*lo
                        mma_bf16(c, al[mt], bh[sub],  bh[sub + 2]);   // lo*hi
                    }
                }
            }
        }

        if (have_next) CP_WAIT0();
        __syncthreads();
    }

    // ---- epilogue: relu, h-store (layer 0), weighted reduce ----
    const int qrow = lane >> 2;
    const int qcol = (lane & 3) * 2;
#pragma unroll
    for (int mt = 0; mt < 2; mt++) {
        const int bl = wm * 2 + mt;
        const int b  = b0 + bl;
        float partial = 0.0f;
#pragma unroll
        for (int nt = 0; nt < 8; nt++) {
#pragma unroll
            for (int r = 0; r < 4; r++) {
                int d = qrow + 8 * (r >> 1);
                int n = n0 + nt * 8 + qcol + (r & 1);
                float v = fmaxf(acc[mt][nt][r], 0.0f);
                if (LAYER == 0) {
                    if (n < 64)
                        g_h[((size_t)b * 64 + n) * 16 + d] = v;
                    else
                        partial = fmaf(v, s_dw[n - 64], partial);
                } else {
                    partial = fmaf(v, s_dw[64 + n], partial);
                }
            }
        }
        atomicAdd(&s_out[bl], partial);
    }
    __syncthreads();
    if (tid < 8) {
        if (LAYER == 0) out[b0 + tid] = s_out[tid] + db[0];
        else            out[b0 + tid] += s_out[tid];
    }
}

// ---------------- launch ----------------
extern "C" void kernel_launch(void* const* d_in, const int* in_sizes, int n_in,
                              void* d_out, int out_size)
{
    const float* x  = (const float*)d_in[0];   // [4096][39][16]
    const float* f0 = (const float*)d_in[1];   // [1521][128]
    const float* f1 = (const float*)d_in[2];   // [2496][128]
    const float* dw = (const float*)d_in[3];   // [192]
    const float* db = (const float*)d_in[4];   // [1]
    float* out = (float*)d_out;                // [4096]

    convert_w_kernel<0><<<(128 * K0PAD + 255) / 256, 256>>>(f0);
    convert_w_kernel<1><<<(128 * K1PAD + 255) / 256, 256>>>(f1);

    constexpr int XT_BYTES = 128 * IPAD * 4;
    constexpr int TILE_B   = 128 * BKP * 2;
    constexpr int BUF_STRIDE = 4 * TILE_B;
    constexpr int OFF_T0 = ((1024 + XT_BYTES + 1023) / 1024) * 1024;
    constexpr int OFF_T1 = ((1024 + XT_BYTES + 128 * JPAD * 4 + 1023) / 1024) * 1024;
    const int smem0 = OFF_T0 + 2 * BUF_STRIDE;   // ~166 KB
    const int smem1 = OFF_T1 + 2 * BUF_STRIDE;   // ~198 KB

    cudaFuncSetAttribute(cin_mma_kernel<39, K0TOT, K0PAD, 0>,
                         cudaFuncAttributeMaxDynamicSharedMemorySize, smem0);
    cudaFuncSetAttribute(cin_mma_kernel<64, K1TOT, K1PAD, 1>,
                         cudaFuncAttributeMaxDynamicSharedMemorySize, smem1);

    dim3 grid(B_TOT / 8);
    dim3 block(NT);
    cin_mma_kernel<39, K0TOT, K0PAD, 0><<<grid, block, smem0>>>(x, dw, db, out);
    cin_mma_kernel<64, K1TOT, K1PAD, 1><<<grid, block, smem1>>>(x, dw, db, out);
}

// round 9
// speedup vs baseline: 1.2205x; 1.2205x over previous
#include <cuda_runtime.h>
#include <cuda_bf16.h>
#include <stdint.h>

// ---------------- problem constants ----------------
#define B_TOT   4096
#define F0N     39
#define DN      16
#define NT      256

#define K0TOT   1521      // 39*39
#define K0PAD   1536      // 48 chunks of 32
#define K1TOT   2496      // 39*64
#define K1PAD   2496      // 78 chunks of 32

#define BK      32        // K per chunk (bf16 elems)
#define BKP     40        // padded row length (bf16) -> 80B stride
#define IPAD    39        // xs_T row stride (floats)
#define JPAD    65        // hs_T row stride (floats)

// ---------------- global scratch ----------------
__device__ float         g_h[B_TOT * 64 * DN];
__device__ __nv_bfloat16 g_w0hi[128 * K0PAD];
__device__ __nv_bfloat16 g_w0lo[128 * K0PAD];
__device__ __nv_bfloat16 g_w1hi[128 * K1PAD];
__device__ __nv_bfloat16 g_w1lo[128 * K1PAD];

// ---------------- PTX helpers ----------------
__device__ __forceinline__ uint32_t smem_to_u32(const void* p) {
    uint32_t a;
    asm("{ .reg .u64 t; cvta.to.shared.u64 t, %1; cvt.u32.u64 %0, t; }" : "=r"(a) : "l"(p));
    return a;
}

__device__ __forceinline__ void ldsm4(uint32_t* r, uint32_t addr) {
    asm volatile("ldmatrix.sync.aligned.m8n8.x4.shared.b16 {%0,%1,%2,%3}, [%4];"
        : "=r"(r[0]), "=r"(r[1]), "=r"(r[2]), "=r"(r[3]) : "r"(addr));
}

__device__ __forceinline__ void mma_bf16(float* c, const uint32_t* a, uint32_t b0, uint32_t b1) {
    asm volatile(
        "mma.sync.aligned.m16n8k16.row.col.f32.bf16.bf16.f32 "
        "{%0,%1,%2,%3}, {%4,%5,%6,%7}, {%8,%9}, {%0,%1,%2,%3};"
        : "+f"(c[0]), "+f"(c[1]), "+f"(c[2]), "+f"(c[3])
        : "r"(a[0]), "r"(a[1]), "r"(a[2]), "r"(a[3]), "r"(b0), "r"(b1));
}

#define CP_ASYNC16(saddr, gptr) \
    asm volatile("cp.async.cg.shared.global [%0], [%1], 16;" \
        :: "r"((uint32_t)(saddr)), "l"(gptr))
#define CP_COMMIT()  asm volatile("cp.async.commit_group;" ::: "memory")
#define CP_WAIT0()   asm volatile("cp.async.wait_group 0;"  ::: "memory")

// ---------------- W pre-split: f[k][128] -> g_w{hi,lo} [n=128][KPAD], zero-padded ----------------
template<int LAYER>
__global__ void __launch_bounds__(256)
convert_w_kernel(const float* __restrict__ f)
{
    constexpr int KTOT = (LAYER == 0) ? K0TOT : K1TOT;
    constexpr int KPAD = (LAYER == 0) ? K0PAD : K1PAD;
    __nv_bfloat16* whi = (LAYER == 0) ? g_w0hi : g_w1hi;
    __nv_bfloat16* wlo = (LAYER == 0) ? g_w0lo : g_w1lo;

    int idx = blockIdx.x * blockDim.x + threadIdx.x;
    if (idx >= 128 * KPAD) return;
    int n = idx / KPAD;
    int k = idx - n * KPAD;
    float v = (k < KTOT) ? f[k * 128 + n] : 0.0f;
    __nv_bfloat16 h = __float2bfloat16_rn(v);
    float r = v - __bfloat162float(h);
    whi[idx] = h;
    wlo[idx] = __float2bfloat16_rn(r);
}

// ---------------- main fused layer kernel (HMMA, 2 CTAs/SM) ----------------
// LAYER 0: h == x (FK=39), writes relu(z[:, :64]) to g_h, out = bias + sum z[:,64:]*dw[0:64]
// LAYER 1: h from g_h (FK=64), out += sum z * dw[64:192]
template<int FK, int KTOT, int KPAD, int LAYER>
__global__ void __launch_bounds__(NT, 2)
cin_mma_kernel(const float* __restrict__ x,
               const float* __restrict__ dw,
               const float* __restrict__ db,
               float* __restrict__ out)
{
    extern __shared__ char smem[];

    constexpr int OFF_DW   = 0;                    // 192 floats
    constexpr int OFF_SOUT = 768;                  // 8 floats
    constexpr int OFF_XT   = 1024;                 // [128][IPAD] floats
    constexpr int XT_BYTES = 128 * IPAD * 4;       // 19968
    constexpr int OFF_HT   = OFF_XT + XT_BYTES;    // 20992
    constexpr int HT_BYTES = (LAYER == 1) ? 128 * JPAD * 4 : 0;
    constexpr int OFF_T    = ((OFF_HT + HT_BYTES + 1023) / 1024) * 1024;
    constexpr int TILE_B   = 128 * BKP * 2;        // 10240
    constexpr int OFF_AHI  = OFF_T;
    constexpr int OFF_ALO  = OFF_T + TILE_B;
    constexpr int OFF_BHI  = OFF_T + 2 * TILE_B;
    constexpr int OFF_BLO  = OFF_T + 3 * TILE_B;
    constexpr int NCHUNKS  = KPAD / BK;

    const __nv_bfloat16* __restrict__ whi = (LAYER == 0) ? g_w0hi : g_w1hi;
    const __nv_bfloat16* __restrict__ wlo = (LAYER == 0) ? g_w0lo : g_w1lo;

    const uint32_t smem_u = smem_to_u32(smem);
    float* s_dw  = (float*)(smem + OFF_DW);
    float* s_out = (float*)(smem + OFF_SOUT);
    float* xt    = (float*)(smem + OFF_XT);
    float* ht    = (LAYER == 0) ? xt : (float*)(smem + OFF_HT);
    constexpr int HSTR = (LAYER == 0) ? IPAD : JPAD;

    const int tid  = threadIdx.x;
    const int wid  = tid >> 5;
    const int lane = tid & 31;
    const int b0   = blockIdx.x * 8;

    // ---- stage x transposed: xt[row][i], row = bl*16 + d ----
    for (int e = tid; e < 8 * F0N * DN; e += NT) {
        int bl = e / (F0N * DN);
        int rem = e - bl * (F0N * DN);
        int i = rem >> 4, d = rem & 15;
        xt[(bl * 16 + d) * IPAD + i] = x[(size_t)(b0) * (F0N * DN) + e];
    }
    if (LAYER == 1) {
        for (int e = tid; e < 8 * 64 * 16; e += NT) {
            int bl = e >> 10;
            int j  = (e >> 4) & 63;
            int d  = e & 15;
            ht[(bl * 16 + d) * JPAD + j] = g_h[(size_t)b0 * 1024 + e];
        }
    }
    if (tid < 192) s_dw[tid] = dw[tid];
    if (tid < 8)   s_out[tid] = 0.0f;
    __syncthreads();

    // warp tiling: 4 (M) x 2 (N); warp tile 32 x 64
    const int wm = wid >> 1;
    const int wn = wid & 1;
    const int m0 = wm * 32;
    const int n0 = wn * 64;

    float acc[2][8][4];
#pragma unroll
    for (int mt = 0; mt < 2; mt++)
#pragma unroll
        for (int nt = 0; nt < 8; nt++)
#pragma unroll
            for (int r = 0; r < 4; r++) acc[mt][nt][r] = 0.0f;

    const int srow = tid >> 2;     // 0..63 (+part*64)
    const int skt  = tid & 3;      // 0..3 (8 bf16 = 16B each)

    const int lrow = (lane & 7) + ((lane >> 3) & 1) * 8;
    const int lkb  = (lane >> 4) * 16;

    for (int ch = 0; ch < NCHUNKS; ch++) {
        const int k0 = ch * BK;

        // ---- B chunk via cp.async (pre-split bf16 [n][KPAD]) ----
#pragma unroll
        for (int p = 0; p < 2; p++) {
            int n = srow + p * 64;
            uint32_t so = (uint32_t)(n * (BKP * 2) + skt * 16);
            CP_ASYNC16(smem_u + OFF_BHI + so, whi + (size_t)n * KPAD + k0 + skt * 8);
            CP_ASYNC16(smem_u + OFF_BLO + so, wlo + (size_t)n * KPAD + k0 + skt * 8);
        }
        CP_COMMIT();

        // ---- build A chunk (hi/lo bf16 split) into padded row-major smem ----
#pragma unroll
        for (int p = 0; p < 2; p++) {
            int row = srow + p * 64;
            int kb  = k0 + skt * 8;
            const float* xr = xt + row * IPAD;
            const float* hr = ht + row * HSTR;
            uint32_t hp[4], lp[4];
#pragma unroll
            for (int v = 0; v < 4; v++) {
                float p0 = 0.0f, p1 = 0.0f;
                int ka = kb + 2 * v;
                if (KPAD == KTOT || ka < KTOT) {
                    int i = ka / FK, j = ka - i * FK;
                    p0 = xr[i] * hr[j];
                }
                if (KPAD == KTOT || (ka + 1) < KTOT) {
                    int i = (ka + 1) / FK, j = (ka + 1) - i * FK;
                    p1 = xr[i] * hr[j];
                }
                __nv_bfloat16 h0 = __float2bfloat16_rn(p0);
                __nv_bfloat16 h1 = __float2bfloat16_rn(p1);
                __nv_bfloat16 e0 = __float2bfloat16_rn(p0 - __bfloat162float(h0));
                __nv_bfloat16 e1 = __float2bfloat16_rn(p1 - __bfloat162float(h1));
                hp[v] = (uint32_t)__bfloat16_as_ushort(h0) | ((uint32_t)__bfloat16_as_ushort(h1) << 16);
                lp[v] = (uint32_t)__bfloat16_as_ushort(e0) | ((uint32_t)__bfloat16_as_ushort(e1) << 16);
            }
            uint32_t so = (uint32_t)(row * (BKP * 2) + skt * 16);
            *(uint4*)(smem + OFF_AHI + so) = make_uint4(hp[0], hp[1], hp[2], hp[3]);
            *(uint4*)(smem + OFF_ALO + so) = make_uint4(lp[0], lp[1], lp[2], lp[3]);
        }

        CP_WAIT0();
        __syncthreads();

        // ---- compute: 2 k16-steps, ldmatrix + mma ----
#pragma unroll
        for (int ks = 0; ks < 2; ks++) {
            const uint32_t kcb = (uint32_t)(ks * 32 + lkb);
            uint32_t ah[2][4], al[2][4];
#pragma unroll
            for (int mt = 0; mt < 2; mt++) {
                uint32_t ra = (uint32_t)((m0 + mt * 16 + lrow) * (BKP * 2)) + kcb;
                ldsm4(ah[mt], smem_u + OFF_AHI + ra);
                ldsm4(al[mt], smem_u + OFF_ALO + ra);
            }
#pragma unroll
            for (int nt2 = 0; nt2 < 4; nt2++) {
                uint32_t rb = (uint32_t)((n0 + nt2 * 16 + lrow) * (BKP * 2)) + kcb;
                uint32_t bh[4], blr[4];
                ldsm4(bh,  smem_u + OFF_BHI + rb);
                ldsm4(blr, smem_u + OFF_BLO + rb);
#pragma unroll
                for (int mt = 0; mt < 2; mt++) {
#pragma unroll
                    for (int sub = 0; sub < 2; sub++) {
                        float* c = acc[mt][nt2 * 2 + sub];
                        mma_bf16(c, ah[mt], bh[sub],  bh[sub + 2]);   // hi*hi
                        mma_bf16(c, ah[mt], blr[sub], blr[sub + 2]);  // hi*lo
                        mma_bf16(c, al[mt], bh[sub],  bh[sub + 2]);   // lo*hi
                    }
                }
            }
        }
        __syncthreads();   // protect smem reuse next chunk
    }

    // ---- epilogue: relu, h-store (layer 0), weighted reduce ----
    const int qrow = lane >> 2;
    const int qcol = (lane & 3) * 2;
#pragma unroll
    for (int mt = 0; mt < 2; mt++) {
        const int bl = wm * 2 + mt;
        const int b  = b0 + bl;
        float partial = 0.0f;
#pragma unroll
        for (int nt = 0; nt < 8; nt++) {
#pragma unroll
            for (int r = 0; r < 4; r++) {
                int d = qrow + 8 * (r >> 1);
                int n = n0 + nt * 8 + qcol + (r & 1);
                float v = fmaxf(acc[mt][nt][r], 0.0f);
                if (LAYER == 0) {
                    if (n < 64)
                        g_h[((size_t)b * 64 + n) * 16 + d] = v;
                    else
                        partial = fmaf(v, s_dw[n - 64], partial);
                } else {
                    partial = fmaf(v, s_dw[64 + n], partial);
                }
            }
        }
        atomicAdd(&s_out[bl], partial);
    }
    __syncthreads();
    if (tid < 8) {
        if (LAYER == 0) out[b0 + tid] = s_out[tid] + db[0];
        else            out[b0 + tid] += s_out[tid];
    }
}

// ---------------- launch ----------------
extern "C" void kernel_launch(void* const* d_in, const int* in_sizes, int n_in,
                              void* d_out, int out_size)
{
    const float* x  = (const float*)d_in[0];   // [4096][39][16]
    const float* f0 = (const float*)d_in[1];   // [1521][128]
    const float* f1 = (const float*)d_in[2];   // [2496][128]
    const float* dw = (const float*)d_in[3];   // [192]
    const float* db = (const float*)d_in[4];   // [1]
    float* out = (float*)d_out;                // [4096]

    convert_w_kernel<0><<<(128 * K0PAD + 255) / 256, 256>>>(f0);
    convert_w_kernel<1><<<(128 * K1PAD + 255) / 256, 256>>>(f1);

    constexpr int XT_BYTES = 128 * IPAD * 4;
    constexpr int TILE_B   = 128 * BKP * 2;
    constexpr int OFF_T0 = ((1024 + XT_BYTES + 1023) / 1024) * 1024;
    constexpr int OFF_T1 = ((1024 + XT_BYTES + 128 * JPAD * 4 + 1023) / 1024) * 1024;
    const int smem0 = OFF_T0 + 4 * TILE_B;   // ~61 KB -> 2+ CTAs/SM
    const int smem1 = OFF_T1 + 4 * TILE_B;   // ~93 KB -> 2 CTAs/SM

    cudaFuncSetAttribute(cin_mma_kernel<39, K0TOT, K0PAD, 0>,
                         cudaFuncAttributeMaxDynamicSharedMemorySize, smem0);
    cudaFuncSetAttribute(cin_mma_kernel<64, K1TOT, K1PAD, 1>,
                         cudaFuncAttributeMaxDynamicSharedMemorySize, smem1);

    dim3 grid(B_TOT / 8);
    dim3 block(NT);
    cin_mma_kernel<39, K0TOT, K0PAD, 0><<<grid, block, smem0>>>(x, dw, db, out);
    cin_mma_kernel<64, K1TOT, K1PAD, 1><<<grid, block, smem1>>>(x, dw, db, out);
}

// round 11
// speedup vs baseline: 1.6530x; 1.3544x over previous
#include <cuda_runtime.h>
#include <cuda_fp16.h>
#include <stdint.h>

// ---------------- problem constants ----------------
#define B_TOT   4096
#define F0N     39
#define DN      16
#define NT      256

#define K0TOT   1521      // 39*39
#define K0PAD   1536      // 48 chunks of 32
#define K1TOT   2496      // 39*64
#define K1PAD   2496      // 78 chunks of 32

#define BK      32        // K per chunk (fp16 elems)
#define ROWB    80        // tile row stride bytes (64B data + 16B pad; 16B-aligned!)
#define IPAD    39        // xs_T row stride (floats)
#define JPAD    65        // hs_T row stride (floats)

// ---------------- global scratch ----------------
__device__ float  g_h[B_TOT * 64 * DN];
__device__ __half g_w0hi[128 * K0PAD];
__device__ __half g_w0lo[128 * K0PAD];
__device__ __half g_w1hi[128 * K1PAD];
__device__ __half g_w1lo[128 * K1PAD];

// ---------------- PTX helpers ----------------
__device__ __forceinline__ uint32_t smem_to_u32(const void* p) {
    uint32_t a;
    asm("{ .reg .u64 t; cvta.to.shared.u64 t, %1; cvt.u32.u64 %0, t; }" : "=r"(a) : "l"(p));
    return a;
}

__device__ __forceinline__ void ldsm4(uint32_t* r, uint32_t addr) {
    asm volatile("ldmatrix.sync.aligned.m8n8.x4.shared.b16 {%0,%1,%2,%3}, [%4];"
        : "=r"(r[0]), "=r"(r[1]), "=r"(r[2]), "=r"(r[3]) : "r"(addr));
}

__device__ __forceinline__ void mma_f16(float* c, const uint32_t* a, uint32_t b0, uint32_t b1) {
    asm volatile(
        "mma.sync.aligned.m16n8k16.row.col.f32.f16.f16.f32 "
        "{%0,%1,%2,%3}, {%4,%5,%6,%7}, {%8,%9}, {%0,%1,%2,%3};"
        : "+f"(c[0]), "+f"(c[1]), "+f"(c[2]), "+f"(c[3])
        : "r"(a[0]), "r"(a[1]), "r"(a[2]), "r"(a[3]), "r"(b0), "r"(b1));
}

#define CP_ASYNC16(saddr, gptr) \
    asm volatile("cp.async.cg.shared.global [%0], [%1], 16;" \
        :: "r"((uint32_t)(saddr)), "l"(gptr))
#define CP_COMMIT()  asm volatile("cp.async.commit_group;" ::: "memory")
#define CP_WAIT0()   asm volatile("cp.async.wait_group 0;"  ::: "memory")

__device__ __forceinline__ uint32_t pack_half2(float p0, float p1) {
    __half2 q = __float22half2_rn(make_float2(p0, p1));
    return *reinterpret_cast<uint32_t*>(&q);
}

// ---------------- W pre-split: f[k][128] -> g_w{hi,lo} fp16 [n=128][KPAD], zero-padded ----------------
template<int LAYER>
__global__ void __launch_bounds__(256)
convert_w_kernel(const float* __restrict__ f)
{
    constexpr int KTOT = (LAYER == 0) ? K0TOT : K1TOT;
    constexpr int KPAD = (LAYER == 0) ? K0PAD : K1PAD;
    __half* whi = (LAYER == 0) ? g_w0hi : g_w1hi;
    __half* wlo = (LAYER == 0) ? g_w0lo : g_w1lo;

    int idx = blockIdx.x * blockDim.x + threadIdx.x;
    if (idx >= 128 * KPAD) return;
    int n = idx / KPAD;
    int k = idx - n * KPAD;
    float v = (k < KTOT) ? f[k * 128 + n] : 0.0f;
    __half h = __float2half_rn(v);
    whi[idx] = h;
    wlo[idx] = __float2half_rn(v - __half2float(h));
}

// ---------------- main fused layer kernel (fp16 HMMA, 2-term, 2 CTAs/SM) ----------------
// LAYER 0: h == x (FK=39), writes relu(z[:, :64]) to g_h, out = bias + sum z[:,64:]*dw[0:64]
// LAYER 1: h from g_h (FK=64), out += sum z * dw[64:192]
template<int FK, int KTOT, int KPAD, int LAYER>
__global__ void __launch_bounds__(NT, 2)
cin_mma_kernel(const float* __restrict__ x,
               const float* __restrict__ dw,
               const float* __restrict__ db,
               float* __restrict__ out)
{
    extern __shared__ char smem[];

    constexpr int OFF_DW   = 0;                    // 192 floats
    constexpr int OFF_SOUT = 768;                  // 8 floats
    constexpr int OFF_XT   = 1024;                 // [128][IPAD] floats
    constexpr int XT_BYTES = 128 * IPAD * 4;       // 19968
    constexpr int OFF_HT   = OFF_XT + XT_BYTES;    // 20992
    constexpr int HT_BYTES = (LAYER == 1) ? 128 * JPAD * 4 : 0;
    constexpr int OFF_T    = ((OFF_HT + HT_BYTES + 1023) / 1024) * 1024;
    constexpr int TILE     = 128 * ROWB;           // 10240
    constexpr int OFF_A    = OFF_T;                // A single-buffered
    constexpr int OFF_B    = OFF_T + TILE;         // B: 2 bufs x (hi, lo)
    constexpr int BBUF     = 2 * TILE;             // per buffer: hi + lo
    constexpr int NCHUNKS  = KPAD / BK;

    const __half* __restrict__ whi = (LAYER == 0) ? g_w0hi : g_w1hi;
    const __half* __restrict__ wlo = (LAYER == 0) ? g_w0lo : g_w1lo;

    const uint32_t smem_u = smem_to_u32(smem);
    float* s_dw  = (float*)(smem + OFF_DW);
    float* s_out = (float*)(smem + OFF_SOUT);
    float* xt    = (float*)(smem + OFF_XT);
    float* ht    = (LAYER == 0) ? xt : (float*)(smem + OFF_HT);
    constexpr int HSTR = (LAYER == 0) ? IPAD : JPAD;

    const int tid  = threadIdx.x;
    const int wid  = tid >> 5;
    const int lane = tid & 31;
    const int b0   = blockIdx.x * 8;

    const int srow = tid >> 2;     // 0..63 (+part*64)
    const int skt  = tid & 3;      // 0..3 (8 fp16 = 16B each)

    // issue B chunk (hi+lo) into buffer pbuf via cp.async
    auto issue_b = [&](int k0n, int pbuf) {
        uint32_t bhi = smem_u + OFF_B + pbuf * BBUF;
        uint32_t blo = bhi + TILE;
#pragma unroll
        for (int p = 0; p < 2; p++) {
            int n = srow + p * 64;
            uint32_t so = (uint32_t)(n * ROWB + skt * 16);
            CP_ASYNC16(bhi + so, whi + (size_t)n * KPAD + k0n + skt * 8);
            CP_ASYNC16(blo + so, wlo + (size_t)n * KPAD + k0n + skt * 8);
        }
    };

    // ---- prefetch B(0) before anything else ----
    issue_b(0, 0);
    CP_COMMIT();

    // ---- stage x transposed: xt[row][i], row = bl*16 + d ----
    for (int e = tid; e < 8 * F0N * DN; e += NT) {
        int bl = e / (F0N * DN);
        int rem = e - bl * (F0N * DN);
        int i = rem >> 4, d = rem & 15;
        xt[(bl * 16 + d) * IPAD + i] = x[(size_t)(b0) * (F0N * DN) + e];
    }
    if (LAYER == 1) {
        for (int e = tid; e < 8 * 64 * 16; e += NT) {
            int bl = e >> 10;
            int j  = (e >> 4) & 63;
            int d  = e & 15;
            ht[(bl * 16 + d) * JPAD + j] = g_h[(size_t)b0 * 1024 + e];
        }
    }
    if (tid < 192) s_dw[tid] = dw[tid];
    if (tid < 8)   s_out[tid] = 0.0f;
    __syncthreads();

    // build A chunk (single fp16) for k-base k0n
    auto build_a = [&](int k0n) {
#pragma unroll
        for (int p = 0; p < 2; p++) {
            int row = srow + p * 64;
            int kb  = k0n + skt * 8;
            const float* xr = xt + row * IPAD;
            const float* hr = ht + row * HSTR;
            uint32_t hp[4];
#pragma unroll
            for (int v = 0; v < 4; v++) {
                float p0 = 0.0f, p1 = 0.0f;
                int ka = kb + 2 * v;
                if (KPAD == KTOT || ka < KTOT) {
                    int i = ka / FK, j = ka - i * FK;
                    p0 = xr[i] * hr[j];
                }
                if (KPAD == KTOT || (ka + 1) < KTOT) {
                    int i = (ka + 1) / FK, j = (ka + 1) - i * FK;
                    p1 = xr[i] * hr[j];
                }
                hp[v] = pack_half2(p0, p1);
            }
            *(uint4*)(smem + OFF_A + row * ROWB + skt * 16) = make_uint4(hp[0], hp[1], hp[2], hp[3]);
        }
    };

    // warp tiling: 4 (M) x 2 (N); warp tile 32 x 64
    const int wm = wid >> 1;
    const int wn = wid & 1;
    const int m0 = wm * 32;
    const int n0 = wn * 64;

    float acc[2][8][4];
#pragma unroll
    for (int mt = 0; mt < 2; mt++)
#pragma unroll
        for (int nt = 0; nt < 8; nt++)
#pragma unroll
            for (int r = 0; r < 4; r++) acc[mt][nt][r] = 0.0f;

    const int lrow = (lane & 7) + ((lane >> 3) & 1) * 8;
    const int lkb  = (lane >> 4) * 16;

    // ---- prologue: A(0); B(0) already in flight ----
    build_a(0);
    CP_WAIT0();
    __syncthreads();

    for (int ch = 0; ch < NCHUNKS; ch++) {
        const int p = ch & 1;
        const bool have_next = (ch + 1 < NCHUNKS);

        // prefetch B(ch+1) into the other buffer; lands during MMA+build below
        if (have_next) { issue_b((ch + 1) * BK, p ^ 1); CP_COMMIT(); }

        // ---- MMA phase on A + B(buf p): 2 k16-steps ----
        const uint32_t bhi_u = smem_u + OFF_B + p * BBUF;
        const uint32_t blo_u = bhi_u + TILE;
#pragma unroll
        for (int ks = 0; ks < 2; ks++) {
            const uint32_t kcb = (uint32_t)(ks * 32 + lkb);
            uint32_t av[2][4];
#pragma unroll
            for (int mt = 0; mt < 2; mt++)
                ldsm4(av[mt], smem_u + OFF_A + (uint32_t)((m0 + mt * 16 + lrow) * ROWB) + kcb);
#pragma unroll
            for (int nt2 = 0; nt2 < 4; nt2++) {
                uint32_t rb = (uint32_t)((n0 + nt2 * 16 + lrow) * ROWB) + kcb;
                uint32_t bh[4], bl[4];
                ldsm4(bh, bhi_u + rb);
                ldsm4(bl, blo_u + rb);
#pragma unroll
                for (int mt = 0; mt < 2; mt++) {
#pragma unroll
                    for (int sub = 0; sub < 2; sub++) {
                        float* c = acc[mt][nt2 * 2 + sub];
                        mma_f16(c, av[mt], bh[sub], bh[sub + 2]);   // A * Bhi
                        mma_f16(c, av[mt], bl[sub], bl[sub + 2]);   // A * Blo
                    }
                }
            }
        }
        __syncthreads();                 // A consumed by all warps

        if (have_next) {
            build_a((ch + 1) * BK);      // overwrite A
            CP_WAIT0();                  // B(ch+1) landed
            __syncthreads();             // A + B(ch+1) visible to all
        }
    }

    // ---- epilogue: relu, h-store (layer 0), weighted reduce ----
    const int qrow = lane >> 2;
    const int qcol = (lane & 3) * 2;
#pragma unroll
    for (int mt = 0; mt < 2; mt++) {
        const int bl = wm * 2 + mt;
        const int b  = b0 + bl;
        float partial = 0.0f;
#pragma unroll
        for (int nt = 0; nt < 8; nt++) {
#pragma unroll
            for (int r = 0; r < 4; r++) {
                int d = qrow + 8 * (r >> 1);
                int n = n0 + nt * 8 + qcol + (r & 1);
                float v = fmaxf(acc[mt][nt][r], 0.0f);
                if (LAYER == 0) {
                    if (n < 64)
                        g_h[((size_t)b * 64 + n) * 16 + d] = v;
                    else
                        partial = fmaf(v, s_dw[n - 64], partial);
                } else {
                    partial = fmaf(v, s_dw[64 + n], partial);
                }
            }
        }
        atomicAdd(&s_out[bl], partial);
    }
    __syncthreads();
    if (tid < 8) {
        if (LAYER == 0) out[b0 + tid] = s_out[tid] + db[0];
        else            out[b0 + tid] += s_out[tid];
    }
}

// ---------------- launch ----------------
extern "C" void kernel_launch(void* const* d_in, const int* in_sizes, int n_in,
                              void* d_out, int out_size)
{
    const float* x  = (const float*)d_in[0];   // [4096][39][16]
    const float* f0 = (const float*)d_in[1];   // [1521][128]
    const float* f1 = (const float*)d_in[2];   // [2496][128]
    const float* dw = (const float*)d_in[3];   // [192]
    const float* db = (const float*)d_in[4];   // [1]
    float* out = (float*)d_out;                // [4096]

    convert_w_kernel<0><<<(128 * K0PAD + 255) / 256, 256>>>(f0);
    convert_w_kernel<1><<<(128 * K1PAD + 255) / 256, 256>>>(f1);

    constexpr int XT_BYTES = 128 * IPAD * 4;
    constexpr int TILE     = 128 * ROWB;
    constexpr int OFF_T0 = ((1024 + XT_BYTES + 1023) / 1024) * 1024;
    constexpr int OFF_T1 = ((1024 + XT_BYTES + 128 * JPAD * 4 + 1023) / 1024) * 1024;
    const int smem0 = OFF_T0 + 5 * TILE;   // ~71 KB -> 2 CTAs/SM
    const int smem1 = OFF_T1 + 5 * TILE;   // ~104 KB -> 2 CTAs/SM

    cudaFuncSetAttribute(cin_mma_kernel<39, K0TOT, K0PAD, 0>,
                         cudaFuncAttributeMaxDynamicSharedMemorySize, smem0);
    cudaFuncSetAttribute(cin_mma_kernel<64, K1TOT, K1PAD, 1>,
                         cudaFuncAttributeMaxDynamicSharedMemorySize, smem1);

    dim3 grid(B_TOT / 8);
    dim3 block(NT);
    cin_mma_kernel<39, K0TOT, K0PAD, 0><<<grid, block, smem0>>>(x, dw, db, out);
    cin_mma_kernel<64, K1TOT, K1PAD, 1><<<grid, block, smem1>>>(x, dw, db, out);
}